// round 1
// baseline (speedup 1.0000x reference)
#include <cuda_runtime.h>
#include <math.h>

#define BB   16
#define CC   256
#define CI   128
#define HWN  4096
#define NP   1024

// ---------------- scratch (static device globals; no allocation) ----------------
__device__ float d_theta[BB * HWN * CI];   // [b][n][ci]
__device__ float d_gf[BB * HWN * CI];      // g conv full res
__device__ float d_pf[BB * HWN * CI];      // phi conv full res
__device__ float d_gp[BB * NP * CI];       // g pooled  [b][m][ci]
__device__ float d_pp[BB * NP * CI];       // phi pooled [b][m][ci]
__device__ float d_yy[BB * HWN * CI];      // attention out [b][n][ci]
__device__ float d_wy[BB * CC * HWN];      // W conv out [b][co][n]
__device__ float d_mean[CC];
__device__ float d_rstd[CC];

// ---------------- conv1x1: out[b][n][ci] = sum_c w[ci][c]*x[b][c][n] + bias[ci] ----------------
// grid (HWN/64, B), block 256. Tile: 64 n x 128 ci, K chunks of 16.
__global__ __launch_bounds__(256) void conv1x1_k(const float* __restrict__ x,
                                                 const float* __restrict__ w,
                                                 const float* __restrict__ bias,
                                                 float* __restrict__ out) {
    __shared__ float xs[16][64];    // [k][n]
    __shared__ float ws[16][128];   // [k][ci]
    const int b = blockIdx.y, n0 = blockIdx.x * 64;
    const int tid = threadIdx.x, tx = tid & 15, ty = tid >> 4;
    const float* xb = x + (size_t)b * CC * HWN;

    float acc[4][8];
#pragma unroll
    for (int i = 0; i < 4; ++i)
#pragma unroll
        for (int j = 0; j < 8; ++j) acc[i][j] = 0.f;

    for (int c0 = 0; c0 < CC; c0 += 16) {
        {   // x tile: 16k x 64n = 256 float4, one per thread
            const int kk = tid >> 4, n4 = tid & 15;
            *(float4*)&xs[kk][n4 * 4] =
                *(const float4*)&xb[(size_t)(c0 + kk) * HWN + n0 + n4 * 4];
        }
#pragma unroll
        for (int it = 0; it < 2; ++it) {    // w tile transpose-load, coalesced along c
            const int li = tid + it * 256;
            const int ci = li >> 2, q = li & 3;
            float4 w4 = *(const float4*)&w[(size_t)ci * CC + c0 + q * 4];
            ws[q * 4 + 0][ci] = w4.x; ws[q * 4 + 1][ci] = w4.y;
            ws[q * 4 + 2][ci] = w4.z; ws[q * 4 + 3][ci] = w4.w;
        }
        __syncthreads();
#pragma unroll
        for (int k = 0; k < 16; ++k) {
            float4 a  = *(const float4*)&xs[k][ty * 4];
            float4 b0 = *(const float4*)&ws[k][tx * 8];
            float4 b1 = *(const float4*)&ws[k][tx * 8 + 4];
            float av[4] = {a.x, a.y, a.z, a.w};
            float bv[8] = {b0.x, b0.y, b0.z, b0.w, b1.x, b1.y, b1.z, b1.w};
#pragma unroll
            for (int i = 0; i < 4; ++i)
#pragma unroll
                for (int j = 0; j < 8; ++j) acc[i][j] += av[i] * bv[j];
        }
        __syncthreads();
    }
#pragma unroll
    for (int i = 0; i < 4; ++i) {
        const int n = n0 + ty * 4 + i;
        float* op = out + (size_t)b * HWN * CI + (size_t)n * CI + tx * 8;
        float4 o0 = make_float4(acc[i][0] + bias[tx * 8 + 0], acc[i][1] + bias[tx * 8 + 1],
                                acc[i][2] + bias[tx * 8 + 2], acc[i][3] + bias[tx * 8 + 3]);
        float4 o1 = make_float4(acc[i][4] + bias[tx * 8 + 4], acc[i][5] + bias[tx * 8 + 5],
                                acc[i][6] + bias[tx * 8 + 6], acc[i][7] + bias[tx * 8 + 7]);
        *(float4*)op = o0;
        *(float4*)(op + 4) = o1;
    }
}

// ---------------- 2x2 maxpool over spatial, channel-last ----------------
__global__ __launch_bounds__(256) void pool_k(const float* __restrict__ in,
                                              float* __restrict__ out) {
    const int gi = blockIdx.x * 256 + threadIdx.x;      // < B*NP*32 (float4 units)
    const int b = gi / (NP * 32);
    const int rem = gi - b * (NP * 32);
    const int m = rem >> 5, k4 = rem & 31;
    const int ph = m >> 5, pw = m & 31;
    const int n00 = ph * 128 + pw * 2;
    const float* ib = in + (size_t)b * HWN * CI + (size_t)n00 * CI + k4 * 4;
    float4 v0 = *(const float4*)ib;
    float4 v1 = *(const float4*)(ib + CI);
    float4 v2 = *(const float4*)(ib + 64 * CI);
    float4 v3 = *(const float4*)(ib + 65 * CI);
    float4 r;
    r.x = fmaxf(fmaxf(v0.x, v1.x), fmaxf(v2.x, v3.x));
    r.y = fmaxf(fmaxf(v0.y, v1.y), fmaxf(v2.y, v3.y));
    r.z = fmaxf(fmaxf(v0.z, v1.z), fmaxf(v2.z, v3.z));
    r.w = fmaxf(fmaxf(v0.w, v1.w), fmaxf(v2.w, v3.w));
    *(float4*)&out[(size_t)b * NP * CI + (size_t)m * CI + k4 * 4] = r;
}

// ---------------- fused attention: y = softmax(theta . phi^T) . g ----------------
// Q = theta [b][4096][128], K = phi pooled [b][1024][128], V = g pooled.
// grid (HWN/64, B), block 256. Flash-style online softmax, KV tiles of 64.
__global__ __launch_bounds__(256) void attn_k(const float* __restrict__ q,
                                              const float* __restrict__ kp,
                                              const float* __restrict__ gp,
                                              float* __restrict__ y) {
    extern __shared__ float sm[];
    float* qs = sm;                 // 64 x 132
    float* ks = qs + 64 * 132;      // 64 x 132
    float* gs = ks + 64 * 132;      // 64 x 128
    float* ps = gs + 64 * 128;      // 64 x 68
    const int b = blockIdx.y, n0 = blockIdx.x * 64;
    const int tid = threadIdx.x, tx = tid & 15, ty = tid >> 4;
    const float* qb = q  + (size_t)b * HWN * CI;
    const float* kb = kp + (size_t)b * NP * CI;
    const float* gb = gp + (size_t)b * NP * CI;

#pragma unroll
    for (int i = 0; i < 8; ++i) {
        const int idx = tid + i * 256;
        const int row = idx >> 5, k4 = idx & 31;
        *(float4*)&qs[row * 132 + k4 * 4] =
            *(const float4*)&qb[(size_t)(n0 + row) * CI + k4 * 4];
    }

    float acc[4][8];
#pragma unroll
    for (int i = 0; i < 4; ++i)
#pragma unroll
        for (int j = 0; j < 8; ++j) acc[i][j] = 0.f;
    float mrow[4] = {-1e30f, -1e30f, -1e30f, -1e30f};
    float lrow[4] = {0.f, 0.f, 0.f, 0.f};

    for (int jt = 0; jt < 16; ++jt) {
        const int m0 = jt * 64;
#pragma unroll
        for (int i = 0; i < 8; ++i) {
            const int idx = tid + i * 256;
            const int row = idx >> 5, k4 = idx & 31;
            *(float4*)&ks[row * 132 + k4 * 4] =
                *(const float4*)&kb[(size_t)(m0 + row) * CI + k4 * 4];
            *(float4*)&gs[row * 128 + k4 * 4] =
                *(const float4*)&gb[(size_t)(m0 + row) * CI + k4 * 4];
        }
        __syncthreads();

        // S = Q Kt  (64x64, thread owns 4 rows x 4 cols)
        float s[4][4];
#pragma unroll
        for (int i = 0; i < 4; ++i)
#pragma unroll
            for (int j = 0; j < 4; ++j) s[i][j] = 0.f;
#pragma unroll 8
        for (int k4 = 0; k4 < 32; ++k4) {
            float4 qv[4], kv[4];
#pragma unroll
            for (int i = 0; i < 4; ++i)
                qv[i] = *(const float4*)&qs[(ty * 4 + i) * 132 + k4 * 4];
#pragma unroll
            for (int j = 0; j < 4; ++j)
                kv[j] = *(const float4*)&ks[(tx * 4 + j) * 132 + k4 * 4];
#pragma unroll
            for (int i = 0; i < 4; ++i)
#pragma unroll
                for (int j = 0; j < 4; ++j)
                    s[i][j] += qv[i].x * kv[j].x + qv[i].y * kv[j].y +
                               qv[i].z * kv[j].z + qv[i].w * kv[j].w;
        }

        // online softmax (row stats replicated across the 16 tx lanes per row)
#pragma unroll
        for (int i = 0; i < 4; ++i) {
            float tm = fmaxf(fmaxf(s[i][0], s[i][1]), fmaxf(s[i][2], s[i][3]));
#pragma unroll
            for (int off = 8; off; off >>= 1)
                tm = fmaxf(tm, __shfl_xor_sync(0xffffffffu, tm, off));
            const float mnew = fmaxf(mrow[i], tm);
            const float scale = __expf(mrow[i] - mnew);
            float psum = 0.f;
#pragma unroll
            for (int j = 0; j < 4; ++j) { s[i][j] = __expf(s[i][j] - mnew); psum += s[i][j]; }
#pragma unroll
            for (int off = 8; off; off >>= 1)
                psum += __shfl_xor_sync(0xffffffffu, psum, off);
            lrow[i] = lrow[i] * scale + psum;
            mrow[i] = mnew;
#pragma unroll
            for (int jj = 0; jj < 8; ++jj) acc[i][jj] *= scale;
            *(float4*)&ps[(ty * 4 + i) * 68 + tx * 4] =
                make_float4(s[i][0], s[i][1], s[i][2], s[i][3]);
        }
        __syncthreads();

        // acc += P * G  (thread owns 4 rows x 8 d-cols)
#pragma unroll 4
        for (int m4 = 0; m4 < 16; ++m4) {
            float pr[4][4];
#pragma unroll
            for (int i = 0; i < 4; ++i) {
                float4 t = *(const float4*)&ps[(ty * 4 + i) * 68 + m4 * 4];
                pr[i][0] = t.x; pr[i][1] = t.y; pr[i][2] = t.z; pr[i][3] = t.w;
            }
#pragma unroll
            for (int u = 0; u < 4; ++u) {
                const int m = m4 * 4 + u;
                float4 ga = *(const float4*)&gs[m * 128 + tx * 8];
                float4 gb4 = *(const float4*)&gs[m * 128 + tx * 8 + 4];
#pragma unroll
                for (int i = 0; i < 4; ++i) {
                    const float p = pr[i][u];
                    acc[i][0] += p * ga.x;  acc[i][1] += p * ga.y;
                    acc[i][2] += p * ga.z;  acc[i][3] += p * ga.w;
                    acc[i][4] += p * gb4.x; acc[i][5] += p * gb4.y;
                    acc[i][6] += p * gb4.z; acc[i][7] += p * gb4.w;
                }
            }
        }
        __syncthreads();
    }

#pragma unroll
    for (int i = 0; i < 4; ++i) {
        const int r = n0 + ty * 4 + i;
        const float inv = 1.f / lrow[i];
        float* op = y + (size_t)b * HWN * CI + (size_t)r * CI + tx * 8;
        *(float4*)op = make_float4(acc[i][0] * inv, acc[i][1] * inv,
                                   acc[i][2] * inv, acc[i][3] * inv);
        *(float4*)(op + 4) = make_float4(acc[i][4] * inv, acc[i][5] * inv,
                                         acc[i][6] * inv, acc[i][7] * inv);
    }
}

// ---------------- W conv: wy[b][co][n] = sum_ci W_w[co][ci]*y[b][n][ci] + W_b[co] ----------------
// grid (HWN/64, C/64, B), block 256. K=128 single pass.
__global__ __launch_bounds__(256) void wconv_k(const float* __restrict__ y,
                                               const float* __restrict__ w,
                                               const float* __restrict__ bias,
                                               float* __restrict__ out) {
    extern __shared__ float sm[];
    float* as = sm;              // 64 x 132 (W rows)
    float* ys = sm + 64 * 132;   // 64 x 132 (y rows)
    const int n0 = blockIdx.x * 64, co0 = blockIdx.y * 64, b = blockIdx.z;
    const int tid = threadIdx.x, tx = tid & 15, ty = tid >> 4;

#pragma unroll
    for (int i = 0; i < 8; ++i) {
        const int idx = tid + i * 256;
        const int row = idx >> 5, k4 = idx & 31;
        *(float4*)&as[row * 132 + k4 * 4] =
            *(const float4*)&w[(size_t)(co0 + row) * CI + k4 * 4];
        *(float4*)&ys[row * 132 + k4 * 4] =
            *(const float4*)&y[(size_t)b * HWN * CI + (size_t)(n0 + row) * CI + k4 * 4];
    }
    __syncthreads();

    float acc[4][4];
#pragma unroll
    for (int i = 0; i < 4; ++i)
#pragma unroll
        for (int j = 0; j < 4; ++j) acc[i][j] = 0.f;
#pragma unroll 8
    for (int k4 = 0; k4 < 32; ++k4) {
        float4 av[4], bv[4];
#pragma unroll
        for (int i = 0; i < 4; ++i)
            av[i] = *(const float4*)&as[(ty * 4 + i) * 132 + k4 * 4];
#pragma unroll
        for (int j = 0; j < 4; ++j)
            bv[j] = *(const float4*)&ys[(tx * 4 + j) * 132 + k4 * 4];
#pragma unroll
        for (int i = 0; i < 4; ++i)
#pragma unroll
            for (int j = 0; j < 4; ++j)
                acc[i][j] += av[i].x * bv[j].x + av[i].y * bv[j].y +
                             av[i].z * bv[j].z + av[i].w * bv[j].w;
    }
#pragma unroll
    for (int i = 0; i < 4; ++i) {
        const int co = co0 + ty * 4 + i;
        const float bb = bias[co];
        *(float4*)&out[(size_t)b * CC * HWN + (size_t)co * HWN + n0 + tx * 4] =
            make_float4(acc[i][0] + bb, acc[i][1] + bb, acc[i][2] + bb, acc[i][3] + bb);
    }
}

// ---------------- BN stats (deterministic, double accumulation) ----------------
__global__ __launch_bounds__(256) void bnstats_k(const float* __restrict__ wy) {
    __shared__ double rs[256], rs2[256];
    const int co = blockIdx.x, tid = threadIdx.x;
    double s = 0.0, s2 = 0.0;
    for (int i = tid; i < BB * HWN; i += 256) {
        const int bb = i >> 12, n = i & 4095;
        const float v = wy[(size_t)bb * CC * HWN + (size_t)co * HWN + n];
        s += (double)v; s2 += (double)v * (double)v;
    }
    rs[tid] = s; rs2[tid] = s2;
    __syncthreads();
    for (int o = 128; o; o >>= 1) {
        if (tid < o) { rs[tid] += rs[tid + o]; rs2[tid] += rs2[tid + o]; }
        __syncthreads();
    }
    if (tid == 0) {
        const double cnt = (double)(BB * HWN);
        const double mean = rs[0] / cnt;
        const double var = rs2[0] / cnt - mean * mean;
        d_mean[co] = (float)mean;
        d_rstd[co] = (float)rsqrt(var + 1e-5);
    }
}

// ---------------- normalize + residual + pack output ----------------
__global__ __launch_bounds__(256) void final_k(const float* __restrict__ wy,
                                               const float* __restrict__ x,
                                               const float* __restrict__ gamma,
                                               const float* __restrict__ beta,
                                               const float* __restrict__ inp0,
                                               float* __restrict__ out, int off) {
    const int gi = blockIdx.x * 256 + threadIdx.x;     // < B*C*HWN/4
    if (gi == 0 && off == 1) out[0] = inp0[0];
    const int base = gi * 4;
    const int co = (base >> 12) & 255;
    const float a = d_rstd[co] * gamma[co];
    const float bconst = beta[co] - d_mean[co] * a;
    float4 wv = *(const float4*)&wy[base];
    float4 xv = *(const float4*)&x[base];
    float* o = out + off + base;
    o[0] = wv.x * a + bconst + xv.x;
    o[1] = wv.y * a + bconst + xv.y;
    o[2] = wv.z * a + bconst + xv.z;
    o[3] = wv.w * a + bconst + xv.w;
}

// ---------------- host launcher ----------------
extern "C" void kernel_launch(void* const* d_in, const int* in_sizes, int n_in,
                              void* d_out, int out_size) {
    const float* inp0 = (const float*)d_in[0];
    const float* x    = (const float*)d_in[1];
    const float* g_w  = (const float*)d_in[2];
    const float* g_b  = (const float*)d_in[3];
    const float* th_w = (const float*)d_in[4];
    const float* th_b = (const float*)d_in[5];
    const float* ph_w = (const float*)d_in[6];
    const float* ph_b = (const float*)d_in[7];
    const float* W_w  = (const float*)d_in[8];
    const float* W_b  = (const float*)d_in[9];
    const float* gam  = (const float*)d_in[10];
    const float* bet  = (const float*)d_in[11];
    float* out = (float*)d_out;

    float *p_theta, *p_gf, *p_pf, *p_gp, *p_pp, *p_yy, *p_wy;
    cudaGetSymbolAddress((void**)&p_theta, d_theta);
    cudaGetSymbolAddress((void**)&p_gf, d_gf);
    cudaGetSymbolAddress((void**)&p_pf, d_pf);
    cudaGetSymbolAddress((void**)&p_gp, d_gp);
    cudaGetSymbolAddress((void**)&p_pp, d_pp);
    cudaGetSymbolAddress((void**)&p_yy, d_yy);
    cudaGetSymbolAddress((void**)&p_wy, d_wy);

    const int ATTN_SMEM  = (64 * 132 * 2 + 64 * 128 + 64 * 68) * 4;  // 117760
    const int WCONV_SMEM = (64 * 132 * 2) * 4;                        // 67584
    cudaFuncSetAttribute(attn_k,  cudaFuncAttributeMaxDynamicSharedMemorySize, ATTN_SMEM);
    cudaFuncSetAttribute(wconv_k, cudaFuncAttributeMaxDynamicSharedMemorySize, WCONV_SMEM);

    dim3 convGrid(HWN / 64, BB);
    conv1x1_k<<<convGrid, 256>>>(x, th_w, th_b, p_theta);
    conv1x1_k<<<convGrid, 256>>>(x, g_w,  g_b,  p_gf);
    conv1x1_k<<<convGrid, 256>>>(x, ph_w, ph_b, p_pf);

    pool_k<<<(BB * NP * 32) / 256, 256>>>(p_gf, p_gp);
    pool_k<<<(BB * NP * 32) / 256, 256>>>(p_pf, p_pp);

    attn_k<<<dim3(HWN / 64, BB), 256, ATTN_SMEM>>>(p_theta, p_pp, p_gp, p_yy);

    wconv_k<<<dim3(HWN / 64, CC / 64, BB), 256, WCONV_SMEM>>>(p_yy, W_w, W_b, p_wy);

    bnstats_k<<<CC, 256>>>(p_wy);

    const int total = BB * CC * HWN;
    const int off = (out_size > total) ? (out_size - total) : 0;
    final_k<<<total / 4 / 256, 256>>>(p_wy, x, gam, bet, inp0, out, off);
}